// round 1
// baseline (speedup 1.0000x reference)
#include <cuda_runtime.h>
#include <cstdint>

#define BB 16
#define TT 128
#define VV 137
#define CC0 3
#define KK 9
#define PADK 4
#define NCLS 226
#define VC (VV*CC0)      // 411
#define TVN (TT*VV)      // 17536

// ---------------- scratch (static device memory; no allocations) ----------------
__device__ float g_A[(size_t)BB*TT*VV*VV];          // 153.8 MB
__device__ float g_buf1[(size_t)BB*256*TT*VV];      // 287 MB
__device__ float g_buf2[(size_t)BB*128*TT*VV];      // 144 MB
__device__ float g_xin[(size_t)BB*CC0*TT*VV];       // 3.4 MB
__device__ float g_scale[VC];
__device__ float g_shift[VC];
__device__ float g_pooled[BB*256];

// ---------------- adjacency: A[b,t,v,w] = exp(-2*||X[b,t,v]-X[b,t,w]||) --------
__global__ __launch_bounds__(256) void adj_kernel(const float* __restrict__ X) {
    int bt = blockIdx.x;                    // b*T + t
    __shared__ float px[VV*3];
    const float* src = X + (size_t)bt * VV * CC0;
    for (int i = threadIdx.x; i < VV*3; i += 256) px[i] = src[i];
    __syncthreads();
    float* out = &g_A[(size_t)bt * VV * VV];
    for (int i = threadIdx.x; i < VV*VV; i += 256) {
        int v = i / VV, w = i % VV;
        float dx = px[v*3+0] - px[w*3+0];
        float dy = px[v*3+1] - px[w*3+1];
        float dz = px[v*3+2] - px[w*3+2];
        float d = sqrtf(dx*dx + dy*dy + dz*dz);
        out[i] = __expf(-2.0f * d);
    }
}

// ---------------- BN stats: per channel (v*C+c) over (b,t) ---------------------
__global__ __launch_bounds__(256) void bn_stats(const float* __restrict__ X,
                                                const float* __restrict__ gamma,
                                                const float* __restrict__ beta) {
    int ch = blockIdx.x;                    // 0..410
    int v = ch / CC0, c = ch % CC0;
    float s = 0.f, s2 = 0.f;
    for (int i = threadIdx.x; i < BB*TT; i += 256) {
        float x = X[((size_t)i * VV + v) * CC0 + c];   // i = b*T+t (contiguous bt)
        s += x; s2 += x * x;
    }
    __shared__ float sh1[8], sh2[8];
    int lane = threadIdx.x & 31, wid = threadIdx.x >> 5;
    #pragma unroll
    for (int o = 16; o > 0; o >>= 1) {
        s  += __shfl_xor_sync(0xffffffffu, s, o);
        s2 += __shfl_xor_sync(0xffffffffu, s2, o);
    }
    if (lane == 0) { sh1[wid] = s; sh2[wid] = s2; }
    __syncthreads();
    if (wid == 0) {
        s  = (lane < 8) ? sh1[lane] : 0.f;
        s2 = (lane < 8) ? sh2[lane] : 0.f;
        #pragma unroll
        for (int o = 4; o > 0; o >>= 1) {
            s  += __shfl_xor_sync(0xffffffffu, s, o);
            s2 += __shfl_xor_sync(0xffffffffu, s2, o);
        }
        if (lane == 0) {
            float inv = 1.0f / (BB*TT);
            float mean = s * inv;
            float var = s2 * inv - mean * mean;
            float sc = gamma[ch] * rsqrtf(var + 1e-5f);
            g_scale[ch] = sc;
            g_shift[ch] = beta[ch] - mean * sc;
        }
    }
}

// ---------------- BN apply + transpose to [B,C,T,V] ----------------------------
__global__ __launch_bounds__(256) void bn_apply(const float* __restrict__ X) {
    int idx = blockIdx.x * 256 + threadIdx.x;
    if (idx >= BB*TT*VV*CC0) return;
    int c = idx % CC0;
    int v = (idx / CC0) % VV;
    int t = (idx / (CC0*VV)) % TT;
    int b = idx / (CC0*VV*TT);
    int ch = v * CC0 + c;
    g_xin[(((size_t)b * CC0 + c) * TT + t) * VV + v] = X[idx] * g_scale[ch] + g_shift[ch];
}

// ---------------- temporal conv (K=9,pad 4 along T), optional relu -------------
// block: (t, b, o_tile of 64). thread = (og 0..7, vg 0..31). thread tile: 8o x 5v
// f32x2 packed FMA: acc pairs adjacent o channels.
template<int CCH>
__global__ __launch_bounds__(256) void conv_temporal(const float* __restrict__ x,
                                                     const float* __restrict__ w,
                                                     const float* __restrict__ bias,
                                                     float* __restrict__ y,
                                                     int Cin, int Cout, int do_relu) {
    const int t = blockIdx.x, b = blockIdx.y, o0 = blockIdx.z * 64;
    __shared__ float ws[CCH*9*64];    // [ci][k][o], o contiguous (for 64-bit pair loads)
    __shared__ float xs[CCH*9*160];   // [ci][k][v], zero-padded to 160
    const int tid = threadIdx.x;
    const int vg = tid & 31, og = tid >> 5;

    unsigned long long acc[4][5];
    #pragma unroll
    for (int u = 0; u < 4; u++)
        #pragma unroll
        for (int j = 0; j < 5; j++) acc[u][j] = 0ull;

    for (int c0 = 0; c0 < Cin; c0 += CCH) {
        for (int i = tid; i < CCH*9*64; i += 256) {
            int o = i & 63; int r = i >> 6; int k = r % 9; int ci = r / 9;
            ws[i] = w[((size_t)(o0 + o) * Cin + (c0 + ci)) * 9 + k];
        }
        for (int i = tid; i < CCH*9*160; i += 256) {
            int v = i % 160; int r = i / 160; int k = r % 9; int ci = r / 9;
            int tt = t + k - PADK;
            float val = 0.f;
            if (v < VV && tt >= 0 && tt < TT)
                val = x[(((size_t)b * Cin + c0 + ci) * TT + tt) * VV + v];
            xs[i] = val;
        }
        __syncthreads();
        #pragma unroll
        for (int ci = 0; ci < CCH; ci++) {
            #pragma unroll
            for (int k = 0; k < 9; k++) {
                const float* xrow = &xs[(ci*9 + k) * 160];
                const float* wrow = &ws[(ci*9 + k) * 64 + og * 8];
                unsigned long long xv2[5];
                #pragma unroll
                for (int j = 0; j < 5; j++) {
                    float xv = xrow[vg + 32*j];
                    asm("mov.b64 %0, {%1,%1};" : "=l"(xv2[j]) : "f"(xv));
                }
                #pragma unroll
                for (int u = 0; u < 4; u++) {
                    unsigned long long w2 =
                        *reinterpret_cast<const unsigned long long*>(&wrow[2*u]);
                    #pragma unroll
                    for (int j = 0; j < 5; j++)
                        asm("fma.rn.f32x2 %0, %1, %2, %0;"
                            : "+l"(acc[u][j]) : "l"(w2), "l"(xv2[j]));
                }
            }
        }
        __syncthreads();
    }
    #pragma unroll
    for (int u = 0; u < 4; u++) {
        int o_lo = o0 + og*8 + 2*u;
        float b_lo = bias[o_lo], b_hi = bias[o_lo + 1];
        #pragma unroll
        for (int j = 0; j < 5; j++) {
            int v = vg + 32*j;
            if (v < VV) {
                float lo, hi;
                asm("mov.b64 {%0,%1}, %2;" : "=f"(lo), "=f"(hi) : "l"(acc[u][j]));
                lo += b_lo; hi += b_hi;
                if (do_relu) { lo = fmaxf(lo, 0.f); hi = fmaxf(hi, 0.f); }
                y[(((size_t)b * Cout + o_lo    ) * TT + t) * VV + v] = lo;
                y[(((size_t)b * Cout + o_lo + 1) * TT + t) * VV + v] = hi;
            }
        }
    }
}

// ---------------- graph matmul: ax[b,c,t,w] = sum_v x[b,c,t,v]*A[b,t,v,w] ------
// block: (t, b, c_tile of 32). thread = (cg 0..7, wi 0..31). thread tile 4c x 5w.
__global__ __launch_bounds__(256) void graphmm(const float* __restrict__ x,
                                               float* __restrict__ y, int Cin) {
    const int t = blockIdx.x, b = blockIdx.y, c0 = blockIdx.z * 32;
    const int tid = threadIdx.x, wi = tid & 31, cg = tid >> 5;
    __shared__ float As[64*160];   // [v][w] padded
    __shared__ float xsm[64*32];   // [v][c], c contiguous for pair loads
    unsigned long long acc2[2][5];
    #pragma unroll
    for (int u = 0; u < 2; u++)
        #pragma unroll
        for (int j = 0; j < 5; j++) acc2[u][j] = 0ull;

    const float* Abt = &g_A[(size_t)(b * TT + t) * VV * VV];
    for (int v0 = 0; v0 < VV; v0 += 64) {
        int vn = min(64, VV - v0);
        for (int i = tid; i < 64*160; i += 256) {
            int v = i / 160, w = i % 160;
            As[i] = (v < vn && w < VV) ? Abt[(size_t)(v0 + v) * VV + w] : 0.f;
        }
        for (int i = tid; i < 64*32; i += 256) {
            int v = i >> 5, c = i & 31;
            xsm[i] = (v < vn) ? x[(((size_t)b * Cin + c0 + c) * TT + t) * VV + v0 + v] : 0.f;
        }
        __syncthreads();
        for (int v = 0; v < vn; v++) {
            unsigned long long a2[5];
            #pragma unroll
            for (int j = 0; j < 5; j++) {
                float a = As[v*160 + wi + 32*j];
                asm("mov.b64 %0, {%1,%1};" : "=l"(a2[j]) : "f"(a));
            }
            #pragma unroll
            for (int u = 0; u < 2; u++) {
                unsigned long long xv2 =
                    *reinterpret_cast<const unsigned long long*>(&xsm[v*32 + cg*4 + 2*u]);
                #pragma unroll
                for (int j = 0; j < 5; j++)
                    asm("fma.rn.f32x2 %0, %1, %2, %0;"
                        : "+l"(acc2[u][j]) : "l"(xv2), "l"(a2[j]));
            }
        }
        __syncthreads();
    }
    #pragma unroll
    for (int u = 0; u < 2; u++) {
        int c_lo = c0 + cg*4 + 2*u;
        #pragma unroll
        for (int j = 0; j < 5; j++) {
            int w = wi + 32*j;
            if (w < VV) {
                float lo, hi;
                asm("mov.b64 {%0,%1}, %2;" : "=f"(lo), "=f"(hi) : "l"(acc2[u][j]));
                y[(((size_t)b * Cin + c_lo    ) * TT + t) * VV + w] = lo;
                y[(((size_t)b * Cin + c_lo + 1) * TT + t) * VV + w] = hi;
            }
        }
    }
}

// ---------------- mean pool over (t,v) -----------------------------------------
__global__ __launch_bounds__(256) void pool_kernel(const float* __restrict__ x) {
    int bc = blockIdx.x;                     // b*256 + c
    const float* p = &x[(size_t)bc * TVN];
    float s = 0.f;
    for (int i = threadIdx.x; i < TVN; i += 256) s += p[i];
    __shared__ float sh[8];
    int lane = threadIdx.x & 31, wid = threadIdx.x >> 5;
    #pragma unroll
    for (int o = 16; o > 0; o >>= 1) s += __shfl_xor_sync(0xffffffffu, s, o);
    if (lane == 0) sh[wid] = s;
    __syncthreads();
    if (wid == 0) {
        s = (lane < 8) ? sh[lane] : 0.f;
        #pragma unroll
        for (int o = 4; o > 0; o >>= 1) s += __shfl_xor_sync(0xffffffffu, s, o);
        if (lane == 0) g_pooled[bc] = s * (1.0f / TVN);
    }
}

// ---------------- FC ------------------------------------------------------------
__global__ __launch_bounds__(256) void fc_kernel(const float* __restrict__ fw,
                                                 const float* __restrict__ fb,
                                                 float* __restrict__ out) {
    int b = blockIdx.x;
    __shared__ float ps[256];
    ps[threadIdx.x] = g_pooled[b * 256 + threadIdx.x];
    __syncthreads();
    int n = threadIdx.x;
    if (n < NCLS) {
        float s = fb[n];
        const float* wr = &fw[(size_t)n * 256];
        #pragma unroll 8
        for (int c = 0; c < 256; c++) s += ps[c] * wr[c];
        out[b * NCLS + n] = s;
    }
}

// ---------------- launch ---------------------------------------------------------
extern "C" void kernel_launch(void* const* d_in, const int* in_sizes, int n_in,
                              void* d_out, int out_size) {
    const float* X     = (const float*)d_in[0];
    const float* gamma = (const float*)d_in[1];
    const float* beta  = (const float*)d_in[2];
    const float* w0 = (const float*)d_in[3];  const float* b0 = (const float*)d_in[4];
    const float* w1 = (const float*)d_in[5];  const float* b1 = (const float*)d_in[6];
    const float* w2 = (const float*)d_in[7];  const float* b2 = (const float*)d_in[8];
    const float* w3 = (const float*)d_in[9];  const float* b3 = (const float*)d_in[10];
    const float* fw = (const float*)d_in[11]; const float* fb = (const float*)d_in[12];
    float* out = (float*)d_out;

    float *xin, *buf1, *buf2;
    cudaGetSymbolAddress((void**)&xin,  g_xin);
    cudaGetSymbolAddress((void**)&buf1, g_buf1);
    cudaGetSymbolAddress((void**)&buf2, g_buf2);

    adj_kernel<<<BB*TT, 256>>>(X);
    bn_stats<<<VC, 256>>>(X, gamma, beta);
    bn_apply<<<(BB*TT*VV*CC0 + 255) / 256, 256>>>(X);

    // conv0: 3 -> 64 (no relu)
    conv_temporal<3><<<dim3(TT, BB, 1), 256>>>(xin, w0, b0, buf1, 3, 64, 0);
    // layer 1: gmm(64) + conv 64->64 relu
    graphmm<<<dim3(TT, BB, 2), 256>>>(buf1, buf2, 64);
    conv_temporal<4><<<dim3(TT, BB, 1), 256>>>(buf2, w1, b1, buf1, 64, 64, 1);
    // layer 2: gmm(64) + conv 64->128 relu
    graphmm<<<dim3(TT, BB, 2), 256>>>(buf1, buf2, 64);
    conv_temporal<4><<<dim3(TT, BB, 2), 256>>>(buf2, w2, b2, buf1, 64, 128, 1);
    // layer 3: gmm(128) + conv 128->256 relu
    graphmm<<<dim3(TT, BB, 4), 256>>>(buf1, buf2, 128);
    conv_temporal<4><<<dim3(TT, BB, 4), 256>>>(buf2, w3, b3, buf1, 128, 256, 1);

    pool_kernel<<<BB*256, 256>>>(buf1);
    fc_kernel<<<BB, 256>>>(fw, fb, out);
}

// round 4
// speedup vs baseline: 2.8746x; 2.8746x over previous
#include <cuda_runtime.h>
#include <cuda_bf16.h>
#include <cstdint>

#define BB 16
#define TT 128
#define VV 137
#define CC0 3
#define PADK 4
#define NCLS 226
#define VC (VV*CC0)       // 411
#define TVN (TT*VV)       // 17536 = 137 * 128
#define NPAD 18816        // 548 halo + 17536 + 548 halo + slack
#define HALO 548
#define NT 137            // n-tiles of 128

// ---------------- scratch (static device memory; no allocations) ----------------
__device__ float g_A[(size_t)BB*TT*VV*VV];                 // 153.8 MB
__device__ float g_y[(size_t)BB*128*TVN];                  // 143.7 MB
__device__ __nv_bfloat16 g_xTh[(size_t)BB*NPAD*128];       // 77 MB (zero halos stay zero)
__device__ __nv_bfloat16 g_xTl[(size_t)BB*NPAD*128];       // 77 MB
__device__ float g_xin[(size_t)BB*CC0*TT*VV];
__device__ __nv_bfloat16 g_wh[9*256*128];
__device__ __nv_bfloat16 g_wl[9*256*128];
__device__ float g_partial[(size_t)BB*256*NT*4];
__device__ float g_scale[VC];
__device__ float g_shift[VC];
__device__ float g_pooled[BB*256];

// ======================= warp-MMA helpers (compute_103-safe) ====================
__device__ __forceinline__ uint32_t smem_to_u32(const void* p) {
    uint32_t a;
    asm("{ .reg .u64 t; cvta.to.shared.u64 t, %1; cvt.u32.u64 %0, t; }" : "=r"(a) : "l"(p));
    return a;
}
__device__ __forceinline__ void ldsm4(uint32_t* r, uint32_t addr) {
    asm volatile("ldmatrix.sync.aligned.m8n8.x4.shared.b16 {%0,%1,%2,%3}, [%4];"
        : "=r"(r[0]), "=r"(r[1]), "=r"(r[2]), "=r"(r[3]) : "r"(addr));
}
__device__ __forceinline__ void mma_bf16(float* d, const uint32_t* a,
                                         uint32_t b0, uint32_t b1) {
    asm volatile("mma.sync.aligned.m16n8k16.row.col.f32.bf16.bf16.f32 "
        "{%0,%1,%2,%3}, {%4,%5,%6,%7}, {%8,%9}, {%0,%1,%2,%3};"
        : "+f"(d[0]), "+f"(d[1]), "+f"(d[2]), "+f"(d[3])
        : "r"(a[0]), "r"(a[1]), "r"(a[2]), "r"(a[3]), "r"(b0), "r"(b1));
}

// ---------------- adjacency -----------------------------------------------------
__global__ __launch_bounds__(256) void adj_kernel(const float* __restrict__ X) {
    int bt = blockIdx.x;
    __shared__ float px[VV*3];
    const float* src = X + (size_t)bt * VV * CC0;
    for (int i = threadIdx.x; i < VV*3; i += 256) px[i] = src[i];
    __syncthreads();
    float* out = &g_A[(size_t)bt * VV * VV];
    for (int i = threadIdx.x; i < VV*VV; i += 256) {
        int v = i / VV, w = i % VV;
        float dx = px[v*3+0] - px[w*3+0];
        float dy = px[v*3+1] - px[w*3+1];
        float dz = px[v*3+2] - px[w*3+2];
        float d = sqrtf(dx*dx + dy*dy + dz*dz);
        out[i] = __expf(-2.0f * d);
    }
}

// ---------------- BN stats / apply ----------------------------------------------
__global__ __launch_bounds__(256) void bn_stats(const float* __restrict__ X,
                                                const float* __restrict__ gamma,
                                                const float* __restrict__ beta) {
    int ch = blockIdx.x;
    int v = ch / CC0, c = ch % CC0;
    float s = 0.f, s2 = 0.f;
    for (int i = threadIdx.x; i < BB*TT; i += 256) {
        float x = X[((size_t)i * VV + v) * CC0 + c];
        s += x; s2 += x * x;
    }
    __shared__ float sh1[8], sh2[8];
    int lane = threadIdx.x & 31, wid = threadIdx.x >> 5;
    #pragma unroll
    for (int o = 16; o > 0; o >>= 1) {
        s  += __shfl_xor_sync(0xffffffffu, s, o);
        s2 += __shfl_xor_sync(0xffffffffu, s2, o);
    }
    if (lane == 0) { sh1[wid] = s; sh2[wid] = s2; }
    __syncthreads();
    if (wid == 0) {
        s  = (lane < 8) ? sh1[lane] : 0.f;
        s2 = (lane < 8) ? sh2[lane] : 0.f;
        #pragma unroll
        for (int o = 4; o > 0; o >>= 1) {
            s  += __shfl_xor_sync(0xffffffffu, s, o);
            s2 += __shfl_xor_sync(0xffffffffu, s2, o);
        }
        if (lane == 0) {
            float inv = 1.0f / (BB*TT);
            float mean = s * inv;
            float var = s2 * inv - mean * mean;
            float sc = gamma[ch] * rsqrtf(var + 1e-5f);
            g_scale[ch] = sc;
            g_shift[ch] = beta[ch] - mean * sc;
        }
    }
}

__global__ __launch_bounds__(256) void bn_apply(const float* __restrict__ X) {
    int idx = blockIdx.x * 256 + threadIdx.x;
    if (idx >= BB*TT*VV*CC0) return;
    int c = idx % CC0;
    int v = (idx / CC0) % VV;
    int t = (idx / (CC0*VV)) % TT;
    int b = idx / (CC0*VV*TT);
    int ch = v * CC0 + c;
    g_xin[(((size_t)b * CC0 + c) * TT + t) * VV + v] = X[idx] * g_scale[ch] + g_shift[ch];
}

// ---------------- conv0 (tiny, CUDA cores, Cin=3, no relu) -----------------------
__global__ __launch_bounds__(256) void conv0_kernel(const float* __restrict__ x,
                                                    const float* __restrict__ w,
                                                    const float* __restrict__ bias,
                                                    float* __restrict__ y) {
    const int t = blockIdx.x, b = blockIdx.y;
    __shared__ float ws[3*9*64];
    __shared__ float xs[3*9*160];
    const int tid = threadIdx.x;
    const int vg = tid & 31, og = tid >> 5;
    unsigned long long acc[4][5];
    #pragma unroll
    for (int u = 0; u < 4; u++)
        #pragma unroll
        for (int j = 0; j < 5; j++) acc[u][j] = 0ull;
    for (int i = tid; i < 3*9*64; i += 256) {
        int o = i & 63; int r = i >> 6; int k = r % 9; int ci = r / 9;
        ws[i] = w[((size_t)o * 3 + ci) * 9 + k];
    }
    for (int i = tid; i < 3*9*160; i += 256) {
        int v = i % 160; int r = i / 160; int k = r % 9; int ci = r / 9;
        int tt = t + k - PADK;
        float val = 0.f;
        if (v < VV && tt >= 0 && tt < TT)
            val = x[(((size_t)b * 3 + ci) * TT + tt) * VV + v];
        xs[i] = val;
    }
    __syncthreads();
    #pragma unroll
    for (int ci = 0; ci < 3; ci++) {
        #pragma unroll
        for (int k = 0; k < 9; k++) {
            const float* xrow = &xs[(ci*9 + k) * 160];
            const float* wrow = &ws[(ci*9 + k) * 64 + og * 8];
            unsigned long long xv2[5];
            #pragma unroll
            for (int j = 0; j < 5; j++) {
                float xv = xrow[vg + 32*j];
                asm("mov.b64 %0, {%1,%1};" : "=l"(xv2[j]) : "f"(xv));
            }
            #pragma unroll
            for (int u = 0; u < 4; u++) {
                unsigned long long w2 = *reinterpret_cast<const unsigned long long*>(&wrow[2*u]);
                #pragma unroll
                for (int j = 0; j < 5; j++)
                    asm("fma.rn.f32x2 %0, %1, %2, %0;" : "+l"(acc[u][j]) : "l"(w2), "l"(xv2[j]));
            }
        }
    }
    #pragma unroll
    for (int u = 0; u < 4; u++) {
        int o_lo = og*8 + 2*u;
        float b_lo = bias[o_lo], b_hi = bias[o_lo + 1];
        #pragma unroll
        for (int j = 0; j < 5; j++) {
            int v = vg + 32*j;
            if (v < VV) {
                float lo, hi;
                asm("mov.b64 {%0,%1}, %2;" : "=f"(lo), "=f"(hi) : "l"(acc[u][j]));
                y[(((size_t)b * 64 + o_lo    ) * TT + t) * VV + v] = lo + b_lo;
                y[(((size_t)b * 64 + o_lo + 1) * TT + t) * VV + v] = hi + b_hi;
            }
        }
    }
}

// ---------------- graph matmul -> split-bf16 n-major output ----------------------
__global__ __launch_bounds__(256) void graphmm(const float* __restrict__ x, int Cin) {
    const int t = blockIdx.x, b = blockIdx.y, c0 = blockIdx.z * 32;
    const int tid = threadIdx.x, wi = tid & 31, cg = tid >> 5;
    __shared__ float As[64*160];
    __shared__ float xsm[64*32];
    unsigned long long acc2[2][5];
    #pragma unroll
    for (int u = 0; u < 2; u++)
        #pragma unroll
        for (int j = 0; j < 5; j++) acc2[u][j] = 0ull;
    const float* Abt = &g_A[(size_t)(b * TT + t) * VV * VV];
    for (int v0 = 0; v0 < VV; v0 += 64) {
        int vn = min(64, VV - v0);
        for (int i = tid; i < 64*160; i += 256) {
            int v = i / 160, w = i % 160;
            As[i] = (v < vn && w < VV) ? Abt[(size_t)(v0 + v) * VV + w] : 0.f;
        }
        for (int i = tid; i < 64*32; i += 256) {
            int v = i >> 5, c = i & 31;
            xsm[i] = (v < vn) ? x[(((size_t)b * Cin + c0 + c) * TT + t) * VV + v0 + v] : 0.f;
        }
        __syncthreads();
        for (int v = 0; v < vn; v++) {
            unsigned long long a2[5];
            #pragma unroll
            for (int j = 0; j < 5; j++) {
                float a = As[v*160 + wi + 32*j];
                asm("mov.b64 %0, {%1,%1};" : "=l"(a2[j]) : "f"(a));
            }
            #pragma unroll
            for (int u = 0; u < 2; u++) {
                unsigned long long xv2 = *reinterpret_cast<const unsigned long long*>(&xsm[v*32 + cg*4 + 2*u]);
                #pragma unroll
                for (int j = 0; j < 5; j++)
                    asm("fma.rn.f32x2 %0, %1, %2, %0;" : "+l"(acc2[u][j]) : "l"(xv2), "l"(a2[j]));
            }
        }
        __syncthreads();
    }
    const size_t rowbase = (size_t)b * NPAD + HALO + (size_t)t * VV;
    #pragma unroll
    for (int u = 0; u < 2; u++) {
        int c_lo = c0 + cg*4 + 2*u;
        #pragma unroll
        for (int j = 0; j < 5; j++) {
            int w = wi + 32*j;
            if (w < VV) {
                float lo, hi;
                asm("mov.b64 {%0,%1}, %2;" : "=f"(lo), "=f"(hi) : "l"(acc2[u][j]));
                __nv_bfloat16 h0 = __float2bfloat16(lo);
                __nv_bfloat16 l0 = __float2bfloat16(lo - __bfloat162float(h0));
                __nv_bfloat16 h1 = __float2bfloat16(hi);
                __nv_bfloat16 l1 = __float2bfloat16(hi - __bfloat162float(h1));
                size_t a = (rowbase + w) * 128 + c_lo;
                __nv_bfloat162 hp; hp.x = h0; hp.y = h1;
                __nv_bfloat162 lp; lp.x = l0; lp.y = l1;
                *reinterpret_cast<__nv_bfloat162*>(&g_xTh[a]) = hp;
                *reinterpret_cast<__nv_bfloat162*>(&g_xTl[a]) = lp;
            }
        }
    }
}

// ---------------- weight prep: fp32 [o][ci][k] -> split bf16 [k][OPAD][ci] ------
__global__ __launch_bounds__(256) void wprep(const float* __restrict__ w,
                                             int Cin, int Cout, int OPAD) {
    int idx = blockIdx.x * 256 + threadIdx.x;
    int total = 9 * OPAD * Cin;
    if (idx >= total) return;
    int ci = idx % Cin;
    int r = idx / Cin;
    int o = r % OPAD;
    int k = r / OPAD;
    float v = (o < Cout) ? w[((size_t)o * Cin + ci) * 9 + k] : 0.f;
    __nv_bfloat16 h = __float2bfloat16(v);
    g_wh[idx] = h;
    g_wl[idx] = __float2bfloat16(v - __bfloat162float(h));
}

// ---------------- warp-MMA temporal conv: M=128(o) x N=128(n), split-bf16 x3 ----
// 8 warps = 2(M) x 4(N); warp tile 64x32; mma.sync m16n8k16 bf16.
// smem rows padded to 72 bf16 (144B) -> conflict-free ldmatrix.
__global__ void __launch_bounds__(256, 1) conv_mma(
    const float* __restrict__ bias, float* __restrict__ yout, float* __restrict__ pout,
    int Cin, int Cout, int OPAD)
{
    extern __shared__ __align__(16) char smem[];
    const uint32_t sb = smem_to_u32(smem);
    const uint32_t offAh = 0, offAl = 18432, offBh = 36864, offBl = 55296;
    const int tid = threadIdx.x;
    const int n0 = blockIdx.x * 128;
    const int b  = blockIdx.y;
    const int o0 = blockIdx.z * 128;
    const int lane = tid & 31, wid = tid >> 5;
    const int wm = wid >> 2, wn = wid & 3;

    float acc[4][4][4];
    #pragma unroll
    for (int mi = 0; mi < 4; mi++)
        #pragma unroll
        for (int ni = 0; ni < 4; ni++)
            #pragma unroll
            for (int r = 0; r < 4; r++) acc[mi][ni][r] = 0.f;

    // per-lane ldmatrix base offsets (bytes), within a 128-row x 144B tile
    const uint32_t a_lane = (uint32_t)(wm*64 + (lane & 15)) * 144 + (uint32_t)(lane >> 4) * 16;
    const uint32_t b_lane = (uint32_t)(wn*32 + (lane & 7) + ((lane >> 4) << 3)) * 144
                          + (uint32_t)((lane >> 3) & 1) * 16;

    for (int k = 0; k < 9; k++) {
        const long long brow = (long long)b * NPAD + HALO + n0 + (long long)(k - 4) * VV;
        for (int c0 = 0; c0 < Cin; c0 += 64) {
            // ---- stage tiles: A (weights) and B (activations), hi+lo ----
            #pragma unroll
            for (int i = tid; i < 1024; i += 256) {
                int r = i >> 3, ch = i & 7;
                uint32_t dst = (uint32_t)r * 144 + (uint32_t)ch * 16;
                size_t asrc = (size_t)(k * OPAD + o0 + r) * Cin + c0 + ch * 8;
                *reinterpret_cast<uint4*>(smem + offAh + dst) = *reinterpret_cast<const uint4*>(g_wh + asrc);
                *reinterpret_cast<uint4*>(smem + offAl + dst) = *reinterpret_cast<const uint4*>(g_wl + asrc);
                size_t bsrc = (size_t)(brow + r) * 128 + c0 + ch * 8;
                *reinterpret_cast<uint4*>(smem + offBh + dst) = *reinterpret_cast<const uint4*>(g_xTh + bsrc);
                *reinterpret_cast<uint4*>(smem + offBl + dst) = *reinterpret_cast<const uint4*>(g_xTl + bsrc);
            }
            __syncthreads();
            // ---- compute: 4 K-chunks of 16 ----
            #pragma unroll
            for (int kk = 0; kk < 4; kk++) {
                const uint32_t koff = (uint32_t)kk * 32;
                uint32_t ah[4][4], al[4][4];
                #pragma unroll
                for (int mi = 0; mi < 4; mi++) {
                    uint32_t ao = a_lane + (uint32_t)mi * (16*144) + koff;
                    ldsm4(ah[mi], sb + offAh + ao);
                    ldsm4(al[mi], sb + offAl + ao);
                }
                uint32_t bh[2][4], bl[2][4];
                #pragma unroll
                for (int g = 0; g < 2; g++) {
                    uint32_t bo = b_lane + (uint32_t)g * (16*144) + koff;
                    ldsm4(bh[g], sb + offBh + bo);
                    ldsm4(bl[g], sb + offBl + bo);
                }
                #pragma unroll
                for (int mi = 0; mi < 4; mi++)
                    #pragma unroll
                    for (int g = 0; g < 2; g++)
                        #pragma unroll
                        for (int hh = 0; hh < 2; hh++) {
                            int ni = g*2 + hh;
                            mma_bf16(acc[mi][ni], ah[mi], bh[g][2*hh], bh[g][2*hh+1]);
                            mma_bf16(acc[mi][ni], ah[mi], bl[g][2*hh], bl[g][2*hh+1]);
                            mma_bf16(acc[mi][ni], al[mi], bh[g][2*hh], bh[g][2*hh+1]);
                        }
            }
            __syncthreads();
        }
    }

    // ---- epilogue ----
    const int mrow = lane >> 2;
    const int ncol = (lane & 3) * 2;
    if (pout) {
        // layer 3: bias + relu + pooled partials per (b, o, tile, wn)
        #pragma unroll
        for (int mi = 0; mi < 4; mi++)
            #pragma unroll
            for (int h = 0; h < 2; h++) {
                int o = o0 + wm*64 + mi*16 + mrow + h*8;
                float bo = bias[o];
                float s = 0.f;
                #pragma unroll
                for (int ni = 0; ni < 4; ni++) {
                    s += fmaxf(acc[mi][ni][2*h+0] + bo, 0.f);
                    s += fmaxf(acc[mi][ni][2*h+1] + bo, 0.f);
                }
                s += __shfl_xor_sync(0xffffffffu, s, 1);
                s += __shfl_xor_sync(0xffffffffu, s, 2);
                if ((lane & 3) == 0)
                    pout[((size_t)(b * 256 + o) * NT + blockIdx.x) * 4 + wn] = s;
            }
    } else {
        // layers 1/2: bias + relu, write fp32 y[b][o][n]
        #pragma unroll
        for (int mi = 0; mi < 4; mi++)
            #pragma unroll
            for (int h = 0; h < 2; h++) {
                int o = o0 + wm*64 + mi*16 + mrow + h*8;
                if (o < Cout) {
                    float bo = bias[o];
                    float* yr = yout + ((size_t)b * Cout + o) * TVN + n0 + wn*32;
                    #pragma unroll
                    for (int ni = 0; ni < 4; ni++) {
                        float2 v;
                        v.x = fmaxf(acc[mi][ni][2*h+0] + bo, 0.f);
                        v.y = fmaxf(acc[mi][ni][2*h+1] + bo, 0.f);
                        *reinterpret_cast<float2*>(yr + ni*8 + ncol) = v;
                    }
                }
            }
    }
}

// ---------------- pool reduce + FC -----------------------------------------------
__global__ __launch_bounds__(256) void pool_reduce() {
    int idx = blockIdx.x * 256 + threadIdx.x;
    if (idx >= BB * 256) return;
    const float* p = &g_partial[(size_t)idx * NT * 4];
    float s = 0.f;
    for (int i = 0; i < NT * 4; i++) s += p[i];
    g_pooled[idx] = s * (1.0f / TVN);
}

__global__ __launch_bounds__(256) void fc_kernel(const float* __restrict__ fw,
                                                 const float* __restrict__ fb,
                                                 float* __restrict__ out) {
    int b = blockIdx.x;
    __shared__ float ps[256];
    ps[threadIdx.x] = g_pooled[b * 256 + threadIdx.x];
    __syncthreads();
    int n = threadIdx.x;
    if (n < NCLS) {
        float s = fb[n];
        const float* wr = &fw[(size_t)n * 256];
        #pragma unroll 8
        for (int c = 0; c < 256; c++) s += ps[c] * wr[c];
        out[b * NCLS + n] = s;
    }
}

// ---------------- launch ----------------------------------------------------------
extern "C" void kernel_launch(void* const* d_in, const int* in_sizes, int n_in,
                              void* d_out, int out_size) {
    const float* X     = (const float*)d_in[0];
    const float* gamma = (const float*)d_in[1];
    const float* beta  = (const float*)d_in[2];
    const float* w0 = (const float*)d_in[3];  const float* b0 = (const float*)d_in[4];
    const float* w1 = (const float*)d_in[5];  const float* b1 = (const float*)d_in[6];
    const float* w2 = (const float*)d_in[7];  const float* b2 = (const float*)d_in[8];
    const float* w3 = (const float*)d_in[9];  const float* b3 = (const float*)d_in[10];
    const float* fw = (const float*)d_in[11]; const float* fb = (const float*)d_in[12];
    float* out = (float*)d_out;

    float *xin, *ybuf, *partial;
    cudaGetSymbolAddress((void**)&xin, g_xin);
    cudaGetSymbolAddress((void**)&ybuf, g_y);
    cudaGetSymbolAddress((void**)&partial, g_partial);

    const int SMEM_CONV = 4 * 18432;   // 73728 B
    cudaFuncSetAttribute(conv_mma, cudaFuncAttributeMaxDynamicSharedMemorySize, SMEM_CONV);

    adj_kernel<<<BB*TT, 256>>>(X);
    bn_stats<<<VC, 256>>>(X, gamma, beta);
    bn_apply<<<(BB*TT*VV*CC0 + 255) / 256, 256>>>(X);

    // conv0: 3 -> 64 (CUDA cores, no relu)
    conv0_kernel<<<dim3(TT, BB), 256>>>(xin, w0, b0, ybuf);

    // layer 1: gmm(64) -> conv 64->64 (+relu)
    graphmm<<<dim3(TT, BB, 2), 256>>>(ybuf, 64);
    wprep<<<(9*128*64 + 255)/256, 256>>>(w1, 64, 64, 128);
    conv_mma<<<dim3(NT, BB, 1), 256, SMEM_CONV>>>(b1, ybuf, nullptr, 64, 64, 128);

    // layer 2: gmm(64) -> conv 64->128 (+relu)
    graphmm<<<dim3(TT, BB, 2), 256>>>(ybuf, 64);
    wprep<<<(9*128*64 + 255)/256, 256>>>(w2, 64, 128, 128);
    conv_mma<<<dim3(NT, BB, 1), 256, SMEM_CONV>>>(b2, ybuf, nullptr, 64, 128, 128);

    // layer 3: gmm(128) -> conv 128->256 (+relu, fused pooling partials)
    graphmm<<<dim3(TT, BB, 4), 256>>>(ybuf, 128);
    wprep<<<(9*256*128 + 255)/256, 256>>>(w3, 128, 256, 256);
    conv_mma<<<dim3(NT, BB, 2), 256, SMEM_CONV>>>(b3, nullptr, partial, 128, 256, 256);

    pool_reduce<<<BB, 256>>>();
    fc_kernel<<<BB, 256>>>(fw, fb, out);
}